// round 17
// baseline (speedup 1.0000x reference)
#include <cuda_runtime.h>
#include <cstdint>
#include <cstddef>

#define Bn 256
#define Ln 1024
#define Vn 40
#define Hn 128
#define NCTA 32            // 8 batch rows per CTA
#define TPB 128

// ---- dynamic smem layout (bytes) ----
// h state: 2 buffers x (hi 2176 + lo 2176); row stride 272 B (68 words)
#define OFF_HB   0
#define HB_BUF   4352
#define HB_LO    2176
#define HROW     272
#define OFF_WOF  8704      // Wo frags: [warp][hi/lo][ks][lane] 16B -> 4*8192
#define OFF_EMB  41472     // emb+bh folded, 40*128 f32
#define OFF_X    61952     // tokens u8 [8][1024]
#define SMEM_SZ  70144

// round-to-nearest-even bf16 split (integer math, matches cvt.rn)
__device__ __forceinline__ void bsplit(float v, uint32_t& h16, uint32_t& l16) {
    uint32_t u = __float_as_uint(v);
    uint32_t r = u + 0x7fffu + ((u >> 16) & 1u);
    h16 = r >> 16;
    float rem = v - __uint_as_float(h16 << 16);
    uint32_t u2 = __float_as_uint(rem);
    uint32_t r2 = u2 + 0x7fffu + ((u2 >> 16) & 1u);
    l16 = r2 >> 16;
}
__device__ __forceinline__ uint32_t pk(uint32_t e, uint32_t o) {   // low=even k
    return e | (o << 16);
}
__device__ __forceinline__ float tanh_fast(float x) {
    float r;
    asm("tanh.approx.f32 %0, %1;" : "=f"(r) : "f"(x));
    return r;
}
__device__ __forceinline__ void mma16816(float* d, const uint32_t* a,
                                         uint32_t b0, uint32_t b1) {
    asm volatile(
        "mma.sync.aligned.m16n8k16.row.col.f32.bf16.bf16.f32 "
        "{%0,%1,%2,%3}, {%4,%5,%6,%7}, {%8,%9}, {%0,%1,%2,%3};"
        : "+f"(d[0]), "+f"(d[1]), "+f"(d[2]), "+f"(d[3])
        : "r"(a[0]), "r"(a[1]), "r"(a[2]), "r"(a[3]), "r"(b0), "r"(b1));
}
// word index within an h row for k-pair p
__device__ __forceinline__ int jword(int p) {
    int ks = p >> 3, r8 = p & 7;
    return ks * 8 + ((r8 & 3) << 1) + (r8 >> 2);
}

__global__ void __launch_bounds__(TPB) rnn_mma_kernel(
    const int* __restrict__ x, const float* __restrict__ h0,
    const float* __restrict__ emb, const float* __restrict__ Wh,
    const float* __restrict__ Wo, const float* __restrict__ bh,
    const float* __restrict__ by, float* __restrict__ out,
    float* __restrict__ final_h)
{
    extern __shared__ __align__(16) char sm[];
    const int t = threadIdx.x, w = t >> 5, lane = t & 31;
    const int g = lane >> 2, c = lane & 3;
    const int bb = blockIdx.x * 8;

    // ---- prologue: emb+bh fold, tokens, by ----
    float* se = (float*)(sm + OFF_EMB);
    for (int i = t; i < Vn * Hn; i += TPB) se[i] = emb[i] + bh[i & 127];
    uint8_t* sx = (uint8_t*)(sm + OFF_X);
    for (int i = t; i < 8 * Ln; i += TPB) {
        int n = i >> 10, l = i & 1023;
        sx[i] = (uint8_t)x[(size_t)(bb + n) * Ln + l];
    }
    const int v0 = 16 * w + g, v1 = v0 + 8;
    float by0 = 0.f, by1 = 0.f;
    if (w < 3) {
        if (v0 < Vn) by0 = by[v0];
        if (v1 < Vn) by1 = by[v1];
    }

    // ---- Wh A-fragments in registers (hi/lo), m16n8k16 row-major map ----
    uint32_t Ah[2][8][4], Al[2][8][4];
#pragma unroll
    for (int mt = 0; mt < 2; mt++)
#pragma unroll
        for (int ks = 0; ks < 8; ks++)
#pragma unroll
            for (int rg = 0; rg < 4; rg++) {
                int row = 32 * w + mt * 16 + g + (rg & 1) * 8;
                int k = ks * 16 + c * 2 + (rg >> 1) * 8;
                float2 p = *(const float2*)(Wh + row * Hn + k);
                uint32_t h0b, l0b, h1b, l1b;
                bsplit(p.x, h0b, l0b);
                bsplit(p.y, h1b, l1b);
                Ah[mt][ks][rg] = pk(h0b, h1b);
                Al[mt][ks][rg] = pk(l0b, l1b);
            }
    // ---- Wo fragments into smem (zero-padded rows >= 40) ----
    if (w < 3) {
#pragma unroll
        for (int ks = 0; ks < 8; ks++) {
            uint32_t fh[4], fl[4];
#pragma unroll
            for (int rg = 0; rg < 4; rg++) {
                int row = 16 * w + g + (rg & 1) * 8;
                int k = ks * 16 + c * 2 + (rg >> 1) * 8;
                float a = (row < Vn) ? Wo[row * Hn + k] : 0.f;
                float b2 = (row < Vn) ? Wo[row * Hn + k + 1] : 0.f;
                uint32_t ha, la, hb2, lb2;
                bsplit(a, ha, la);
                bsplit(b2, hb2, lb2);
                fh[rg] = pk(ha, hb2);
                fl[rg] = pk(la, lb2);
            }
            *(uint4*)(sm + OFF_WOF + w * 8192 + ks * 512 + lane * 16) =
                make_uint4(fh[0], fh[1], fh[2], fh[3]);
            *(uint4*)(sm + OFF_WOF + w * 8192 + 4096 + ks * 512 + lane * 16) =
                make_uint4(fl[0], fl[1], fl[2], fl[3]);
        }
    }
    // ---- h state init (buffer 0) ----
    for (int i = t; i < 8 * Hn; i += TPB) {
        int n = i >> 7, m = i & 127;
        float v = h0[(size_t)(bb + n) * Hn + m];
        uint32_t hh, ll;
        bsplit(v, hh, ll);
        int off = n * HROW + jword(m >> 1) * 4 + (m & 1) * 2;
        *(uint16_t*)(sm + OFF_HB + off) = (uint16_t)hh;
        *(uint16_t*)(sm + OFF_HB + HB_LO + off) = (uint16_t)ll;
    }

    // ---- per-lane invariant addresses ----
    const int rboff = g * HROW + c * 8;            // B-frag LDS.64 base
    uint32_t wa[8];                                 // finalize store offsets
#pragma unroll
    for (int mt = 0; mt < 2; mt++)
#pragma unroll
        for (int j = 0; j < 4; j++) {
            int m = 32 * w + mt * 16 + g + (j >> 1) * 8;
            int n = 2 * c + (j & 1);
            wa[mt * 4 + j] = n * HROW + jword(m >> 1) * 4 + (m & 1) * 2;
        }
    // logit out pointers (store row l-1 at iter l)
    float* po0 = out + ((size_t)(bb + 2 * c) * Ln) * Vn + v0 - Vn;
    float* po1 = out + ((size_t)(bb + 2 * c + 1) * Ln) * Vn + v0 - Vn;

    __syncthreads();

#pragma unroll 1
    for (int l = 0; l < Ln; l++) {
        const char* rb = sm + OFF_HB + (l & 1) * HB_BUF;
        const int t0 = sx[(2 * c) * Ln + l];
        const int t1 = sx[(2 * c + 1) * Ln + l];

        float Dh[2][4] = {{0.f, 0.f, 0.f, 0.f}, {0.f, 0.f, 0.f, 0.f}};
        float Do[4] = {0.f, 0.f, 0.f, 0.f};
        const char* wof = sm + OFF_WOF + w * 8192;

#pragma unroll
        for (int ks = 0; ks < 8; ks++) {
            uint2 bhh = *(const uint2*)(rb + rboff + ks * 32);
            uint2 bll = *(const uint2*)(rb + HB_LO + rboff + ks * 32);
            mma16816(Dh[0], Ah[0][ks], bhh.x, bhh.y);
            mma16816(Dh[1], Ah[1][ks], bhh.x, bhh.y);
            mma16816(Dh[0], Ah[0][ks], bll.x, bll.y);
            mma16816(Dh[1], Ah[1][ks], bll.x, bll.y);
            mma16816(Dh[0], Al[0][ks], bhh.x, bhh.y);
            mma16816(Dh[1], Al[1][ks], bhh.x, bhh.y);
            if (w < 3) {
                uint4 wh4 = *(const uint4*)(wof + ks * 512 + lane * 16);
                uint4 wl4 = *(const uint4*)(wof + 4096 + ks * 512 + lane * 16);
                uint32_t ah[4] = {wh4.x, wh4.y, wh4.z, wh4.w};
                uint32_t al2[4] = {wl4.x, wl4.y, wl4.z, wl4.w};
                mma16816(Do, ah, bhh.x, bhh.y);
                mma16816(Do, ah, bll.x, bll.y);
                mma16816(Do, al2, bhh.x, bhh.y);
            }
        }

        // embedding terms for this step's finalize
        float ev[8];
#pragma unroll
        for (int mt = 0; mt < 2; mt++)
#pragma unroll
            for (int j = 0; j < 4; j++) {
                int m = 32 * w + mt * 16 + g + (j >> 1) * 8;
                ev[mt * 4 + j] = se[((j & 1) ? t1 : t0) * Hn + m];
            }

        // finalize h_l -> write frag-layout bf16 hi/lo into other buffer
        char* wb = sm + OFF_HB + ((l + 1) & 1) * HB_BUF;
#pragma unroll
        for (int mt = 0; mt < 2; mt++)
#pragma unroll
            for (int j = 0; j < 4; j++) {
                const int q = mt * 4 + j;
                float hv = tanh_fast(Dh[mt][j] + ev[q]);
                uint32_t hh, ll;
                bsplit(hv, hh, ll);
                *(uint16_t*)(wb + wa[q]) = (uint16_t)hh;
                *(uint16_t*)(wb + HB_LO + wa[q]) = (uint16_t)ll;
                if (l == Ln - 1) {
                    int m = 32 * w + mt * 16 + g + (j >> 1) * 8;
                    int n = 2 * c + (j & 1);
                    final_h[(size_t)(bb + n) * Hn + m] = hv;
                }
            }

        // logits row l-1 (from B = h_{l-1})
        if (w < 3 && l > 0) {
            if (v0 < Vn) {
                po0[0] = Do[0] + by0;
                po1[0] = Do[1] + by0;
            }
            if (v1 < Vn) {
                po0[8] = Do[2] + by1;
                po1[8] = Do[3] + by1;
            }
        }
        po0 += Vn;
        po1 += Vn;
        __syncthreads();
    }

    // ---- epilogue: logit row Ln-1 from h_{Ln-1} (buffer 0) ----
    if (w < 3) {
        const char* rb = sm + OFF_HB;   // (Ln & 1) == 0
        const char* wof = sm + OFF_WOF + w * 8192;
        float Do[4] = {0.f, 0.f, 0.f, 0.f};
#pragma unroll
        for (int ks = 0; ks < 8; ks++) {
            uint2 bhh = *(const uint2*)(rb + rboff + ks * 32);
            uint2 bll = *(const uint2*)(rb + HB_LO + rboff + ks * 32);
            uint4 wh4 = *(const uint4*)(wof + ks * 512 + lane * 16);
            uint4 wl4 = *(const uint4*)(wof + 4096 + ks * 512 + lane * 16);
            uint32_t ah[4] = {wh4.x, wh4.y, wh4.z, wh4.w};
            uint32_t al2[4] = {wl4.x, wl4.y, wl4.z, wl4.w};
            mma16816(Do, ah, bhh.x, bhh.y);
            mma16816(Do, ah, bll.x, bll.y);
            mma16816(Do, al2, bhh.x, bhh.y);
        }
        if (v0 < Vn) {
            po0[0] = Do[0] + by0;
            po1[0] = Do[1] + by0;
        }
        if (v1 < Vn) {
            po0[8] = Do[2] + by1;
            po1[8] = Do[3] + by1;
        }
    }
}

extern "C" void kernel_launch(void* const* d_in, const int* in_sizes, int n_in,
                              void* d_out, int out_size)
{
    const int*   x   = (const int*)d_in[0];
    const float* h0  = (const float*)d_in[1];
    const float* emb = (const float*)d_in[2];
    const float* Wh  = (const float*)d_in[3];
    const float* Wo  = (const float*)d_in[4];
    const float* bh  = (const float*)d_in[5];
    const float* by  = (const float*)d_in[6];

    float* out     = (float*)d_out;
    float* logits  = out;                               // [B, L, V]
    float* final_h = out + (size_t)Bn * Ln * Vn;        // [B, H]

    static int attr_set = 0;
    if (!attr_set) {
        cudaFuncSetAttribute(rnn_mma_kernel,
                             cudaFuncAttributeMaxDynamicSharedMemorySize,
                             SMEM_SZ);
        attr_set = 1;
    }
    rnn_mma_kernel<<<NCTA, TPB, SMEM_SZ>>>(x, h0, emb, Wh, Wo, bh, by,
                                           logits, final_h);
}